// round 9
// baseline (speedup 1.0000x reference)
#include <cuda_runtime.h>
#include <cuda_bf16.h>

// PackedAvgPool1d: out[t, :] = sum_{i<min(rem[t],K)} x[base[t]+i, :] / min(rem[t],K)
// D = 768 floats per row = 192 float4.
//
// Persistent grid-stride version: 148*8 CTAs, each loops over groups of
// TPB=4 tokens. R3/R7 showed a hard plateau at ~6.33 TB/s (LTS cap);
// the remaining recoverable time is the multi-wave launch/drain overhead
// (~8 waves -> 1 persistent wave). Per-iteration structure is the proven
// R7 fast path: 8 unpredicated front-batched LDG.128s per thread.

#define DIM 768
#define CPR (DIM / 4)   // float4 per row = 192
#define TPB 4           // tokens per group
#define NBLK (148 * 8)  // persistent grid: one wave at occupancy 8

__global__ __launch_bounds__(CPR, 8) void packed_avgpool1d_kernel(
    const float4* __restrict__ x,      // [Tx, CPR]
    const int*    __restrict__ base,   // [Ty]
    const int*    __restrict__ rem,    // [Ty]
    const int*    __restrict__ kptr,   // scalar
    float4*       __restrict__ out,    // [Ty, CPR]
    int Ty, int Tx)
{
    const int c       = threadIdx.x;
    const int K       = __ldg(kptr);
    const int ngroups = (Ty + TPB - 1) / TPB;

    for (int g = blockIdx.x; g < ngroups; g += NBLK) {
        const int t0 = g * TPB;

        if (K == 2 && t0 + TPB <= Ty) {
            // Fast path: K=2, full group of 4 tokens.
            int b[TPB], r[TPB];
            #pragma unroll
            for (int u = 0; u < TPB; ++u) {
                b[u] = __ldg(&base[t0 + u]);
                r[u] = __ldg(&rem[t0 + u]);
            }

            // Front-batch all 8 row loads, unpredicated; second-row index
            // clamped in-bounds, masked arithmetically below.
            float4 v0[TPB], v1[TPB];
            #pragma unroll
            for (int u = 0; u < TPB; ++u)
                v0[u] = __ldg(&x[(long long)b[u] * CPR + c]);
            #pragma unroll
            for (int u = 0; u < TPB; ++u) {
                const int b1 = min(b[u] + 1, Tx - 1);
                v1[u] = __ldg(&x[(long long)b1 * CPR + c]);
            }

            #pragma unroll
            for (int u = 0; u < TPB; ++u) {
                const bool two = (r[u] > 1);
                const float w1  = two ? 1.0f : 0.0f;
                const float inv = two ? 0.5f : 1.0f;
                float4 o;
                o.x = (v0[u].x + w1 * v1[u].x) * inv;
                o.y = (v0[u].y + w1 * v1[u].y) * inv;
                o.z = (v0[u].z + w1 * v1[u].z) * inv;
                o.w = (v0[u].w + w1 * v1[u].w) * inv;
                out[(long long)(t0 + u) * CPR + c] = o;
            }
        } else {
            // Generic / tail path: arbitrary K, partial group.
            for (int u = 0; u < TPB; ++u) {
                const int t = t0 + u;
                if (t >= Ty) break;
                const int b = __ldg(&base[t]);
                const int r = __ldg(&rem[t]);

                float4 acc = make_float4(0.f, 0.f, 0.f, 0.f);
                for (int k = 0; k < K; ++k) {
                    if (k < r) {
                        float4 v = __ldg(&x[(long long)(b + k) * CPR + c]);
                        acc.x += v.x; acc.y += v.y; acc.z += v.z; acc.w += v.w;
                    }
                }
                const int cnt = min(r, K);          // >= 1 by construction
                const float inv = 1.0f / (float)cnt;
                acc.x *= inv; acc.y *= inv; acc.z *= inv; acc.w *= inv;
                out[(long long)t * CPR + c] = acc;
            }
        }
    }
}

extern "C" void kernel_launch(void* const* d_in, const int* in_sizes, int n_in,
                              void* d_out, int out_size)
{
    const float4* x    = (const float4*)d_in[0];
    const int*    base = (const int*)d_in[1];
    const int*    rem  = (const int*)d_in[2];
    const int*    kptr = (const int*)d_in[3];
    float4*       out  = (float4*)d_out;

    const int Ty = in_sizes[1];          // one entry per output token
    const int Tx = in_sizes[0] / DIM;    // input rows
    const int ngroups = (Ty + TPB - 1) / TPB;
    const int nblk = ngroups < NBLK ? ngroups : NBLK;

    packed_avgpool1d_kernel<<<nblk, CPR>>>(x, base, rem, kptr, out, Ty, Tx);
}

// round 10
// speedup vs baseline: 1.0557x; 1.0557x over previous
#include <cuda_runtime.h>
#include <cuda_bf16.h>

// PackedAvgPool1d: out[t, :] = sum_{i<min(rem[t],K)} x[base[t]+i, :] / min(rem[t],K)
// D = 768 floats per row = 192 float4.
//
// Best measured structure (R7): multi-wave grid, TPB=4, 192 threads,
// 8 unpredicated front-batched LDG.128 per thread (clamped second-row
// index, arithmetic rem-mask). Three structural variants all plateau at
// ~6.3 TB/s = chip streaming ceiling, so this round only adds touch-once
// cache hints: __ldcs on the x stream, __stcs on the output stream.

#define DIM 768
#define CPR (DIM / 4)   // float4 per row = 192
#define TPB 4           // tokens per block

__global__ __launch_bounds__(CPR, 8) void packed_avgpool1d_kernel(
    const float4* __restrict__ x,      // [Tx, CPR]
    const int*    __restrict__ base,   // [Ty]
    const int*    __restrict__ rem,    // [Ty]
    const int*    __restrict__ kptr,   // scalar
    float4*       __restrict__ out,    // [Ty, CPR]
    int Ty, int Tx)
{
    const int c  = threadIdx.x;
    const int t0 = blockIdx.x * TPB;
    const int K  = __ldg(kptr);

    if (K == 2 && t0 + TPB <= Ty) {
        // Fast path: K=2, full group of 4 tokens.
        int b[TPB], r[TPB];
        #pragma unroll
        for (int u = 0; u < TPB; ++u) {
            b[u] = __ldg(&base[t0 + u]);
            r[u] = __ldg(&rem[t0 + u]);
        }

        // Front-batch all 8 row loads, unpredicated, streaming (touch-once).
        float4 v0[TPB], v1[TPB];
        #pragma unroll
        for (int u = 0; u < TPB; ++u)
            v0[u] = __ldcs(&x[(long long)b[u] * CPR + c]);
        #pragma unroll
        for (int u = 0; u < TPB; ++u) {
            const int b1 = min(b[u] + 1, Tx - 1);
            v1[u] = __ldcs(&x[(long long)b1 * CPR + c]);
        }

        #pragma unroll
        for (int u = 0; u < TPB; ++u) {
            const bool two = (r[u] > 1);
            const float w1  = two ? 1.0f : 0.0f;   // include second row?
            const float inv = two ? 0.5f : 1.0f;
            float4 o;
            o.x = (v0[u].x + w1 * v1[u].x) * inv;
            o.y = (v0[u].y + w1 * v1[u].y) * inv;
            o.z = (v0[u].z + w1 * v1[u].z) * inv;
            o.w = (v0[u].w + w1 * v1[u].w) * inv;
            __stcs(&out[(long long)(t0 + u) * CPR + c], o);
        }
    } else {
        // Generic / tail path: arbitrary K, partial group.
        for (int u = 0; u < TPB; ++u) {
            const int t = t0 + u;
            if (t >= Ty) break;
            const int b = __ldg(&base[t]);
            const int r = __ldg(&rem[t]);

            float4 acc = make_float4(0.f, 0.f, 0.f, 0.f);
            for (int k = 0; k < K; ++k) {
                if (k < r) {
                    float4 v = __ldcs(&x[(long long)(b + k) * CPR + c]);
                    acc.x += v.x; acc.y += v.y; acc.z += v.z; acc.w += v.w;
                }
            }
            const int cnt = min(r, K);          // >= 1 by construction
            const float inv = 1.0f / (float)cnt;
            acc.x *= inv; acc.y *= inv; acc.z *= inv; acc.w *= inv;
            __stcs(&out[(long long)t * CPR + c], acc);
        }
    }
}

extern "C" void kernel_launch(void* const* d_in, const int* in_sizes, int n_in,
                              void* d_out, int out_size)
{
    const float4* x    = (const float4*)d_in[0];
    const int*    base = (const int*)d_in[1];
    const int*    rem  = (const int*)d_in[2];
    const int*    kptr = (const int*)d_in[3];
    float4*       out  = (float4*)d_out;

    const int Ty = in_sizes[1];          // one entry per output token
    const int Tx = in_sizes[0] / DIM;    // input rows
    const int nblk = (Ty + TPB - 1) / TPB;

    packed_avgpool1d_kernel<<<nblk, CPR>>>(x, base, rem, kptr, out, Ty, Tx);
}

// round 11
// speedup vs baseline: 1.0612x; 1.0052x over previous
#include <cuda_runtime.h>
#include <cuda_bf16.h>

// PackedAvgPool1d: out[t, :] = sum_{i<min(rem[t],K)} x[base[t]+i, :] / min(rem[t],K)
// D = 768 floats per row = 192 float4.
//
// R7 structure (best measured: TPB=4, 8 unpredicated front-batched
// LDG.128/thread, plain loads/stores — __ldcs/__stcs regressed).
// Key fix: __launch_bounds__(192, 5). The previous (192, 8) capped
// ptxas at 42 regs/thread, forcing the 8-float4 batch (needs ~56 regs
// live) to be re-serialized. Cap 68 regs lets the whole batch stay in
// flight; 5 CTAs/SM = 30 warps x 8 loads = 240 outstanding per SM.

#define DIM 768
#define CPR (DIM / 4)   // float4 per row = 192
#define TPB 4           // tokens per block

__global__ __launch_bounds__(CPR, 5) void packed_avgpool1d_kernel(
    const float4* __restrict__ x,      // [Tx, CPR]
    const int*    __restrict__ base,   // [Ty]
    const int*    __restrict__ rem,    // [Ty]
    const int*    __restrict__ kptr,   // scalar
    float4*       __restrict__ out,    // [Ty, CPR]
    int Ty, int Tx)
{
    const int c  = threadIdx.x;
    const int t0 = blockIdx.x * TPB;
    const int K  = __ldg(kptr);

    if (K == 2 && t0 + TPB <= Ty) {
        // Fast path: K=2, full group of 4 tokens.
        int b[TPB], r[TPB];
        #pragma unroll
        for (int u = 0; u < TPB; ++u) {
            b[u] = __ldg(&base[t0 + u]);
            r[u] = __ldg(&rem[t0 + u]);
        }

        // Front-batch all 8 row loads, unpredicated; second-row index
        // clamped in-bounds, masked arithmetically below.
        float4 v0[TPB], v1[TPB];
        #pragma unroll
        for (int u = 0; u < TPB; ++u)
            v0[u] = __ldg(&x[(long long)b[u] * CPR + c]);
        #pragma unroll
        for (int u = 0; u < TPB; ++u) {
            const int b1 = min(b[u] + 1, Tx - 1);
            v1[u] = __ldg(&x[(long long)b1 * CPR + c]);
        }

        #pragma unroll
        for (int u = 0; u < TPB; ++u) {
            const bool two = (r[u] > 1);
            const float w1  = two ? 1.0f : 0.0f;   // include second row?
            const float inv = two ? 0.5f : 1.0f;
            float4 o;
            o.x = (v0[u].x + w1 * v1[u].x) * inv;
            o.y = (v0[u].y + w1 * v1[u].y) * inv;
            o.z = (v0[u].z + w1 * v1[u].z) * inv;
            o.w = (v0[u].w + w1 * v1[u].w) * inv;
            out[(long long)(t0 + u) * CPR + c] = o;
        }
    } else {
        // Generic / tail path: arbitrary K, partial group.
        for (int u = 0; u < TPB; ++u) {
            const int t = t0 + u;
            if (t >= Ty) break;
            const int b = __ldg(&base[t]);
            const int r = __ldg(&rem[t]);

            float4 acc = make_float4(0.f, 0.f, 0.f, 0.f);
            for (int k = 0; k < K; ++k) {
                if (k < r) {
                    float4 v = __ldg(&x[(long long)(b + k) * CPR + c]);
                    acc.x += v.x; acc.y += v.y; acc.z += v.z; acc.w += v.w;
                }
            }
            const int cnt = min(r, K);          // >= 1 by construction
            const float inv = 1.0f / (float)cnt;
            acc.x *= inv; acc.y *= inv; acc.z *= inv; acc.w *= inv;
            out[(long long)t * CPR + c] = acc;
        }
    }
}

extern "C" void kernel_launch(void* const* d_in, const int* in_sizes, int n_in,
                              void* d_out, int out_size)
{
    const float4* x    = (const float4*)d_in[0];
    const int*    base = (const int*)d_in[1];
    const int*    rem  = (const int*)d_in[2];
    const int*    kptr = (const int*)d_in[3];
    float4*       out  = (float4*)d_out;

    const int Ty = in_sizes[1];          // one entry per output token
    const int Tx = in_sizes[0] / DIM;    // input rows
    const int nblk = (Ty + TPB - 1) / TPB;

    packed_avgpool1d_kernel<<<nblk, CPR>>>(x, base, rem, kptr, out, Ty, Tx);
}